// round 1
// baseline (speedup 1.0000x reference)
#include <cuda_runtime.h>
#include <math.h>

#define NN    4096
#define IN_F  256
#define H     8
#define D     64
#define HD    (H * D)          // 512
#define INV_SCALE 0.25f        // 1 / (8.0 * 0.5)

// Scratch (allocation-free rule: __device__ globals)
__device__ float g_Q[NN * HD];                       // 8 MB
__device__ float g_K[NN * HD];                       // 8 MB
__device__ float g_S[(size_t)H * NN * NN];           // 512 MB

// ---------------------------------------------------------------------------
// Kernel 1: Q/K projection.  Y = X @ W + b.  blockIdx.z: 0 -> Q, 1 -> K.
// Tiles: BM=64, BN=64, BK=16; 256 threads; 4x4 micro-tile per thread.
// ---------------------------------------------------------------------------
__global__ void proj_kernel(const float* __restrict__ X,
                            const float* __restrict__ Wq, const float* __restrict__ bq,
                            const float* __restrict__ Wk, const float* __restrict__ bk)
{
    const float* W = (blockIdx.z == 0) ? Wq : Wk;
    const float* b = (blockIdx.z == 0) ? bq : bk;
    float*       O = (blockIdx.z == 0) ? g_Q : g_K;

    __shared__ float As[16][68];   // As[k][i] = X[row0+i][k0+k]
    __shared__ float Bs[16][68];   // Bs[k][j] = W[k0+k][col0+j]

    const int tid  = threadIdx.x;          // 0..255
    const int row0 = blockIdx.y * 64;
    const int col0 = blockIdx.x * 64;
    const int tx   = tid & 15;             // 0..15 (cols)
    const int ty   = tid >> 4;             // 0..15 (rows)

    float acc[4][4] = {};

    for (int k0 = 0; k0 < IN_F; k0 += 16) {
        #pragma unroll
        for (int l = 0; l < 4; l++) {
            int e = tid + l * 256;         // 0..1023
            int k = e & 15, i = e >> 4;    // coalesced 16-float chunks of X rows
            As[k][i] = X[(row0 + i) * IN_F + k0 + k];
        }
        #pragma unroll
        for (int l = 0; l < 4; l++) {
            int e = tid + l * 256;
            int j = e & 63, k = e >> 6;    // coalesced rows of W
            Bs[k][j] = W[(k0 + k) * HD + col0 + j];
        }
        __syncthreads();
        #pragma unroll
        for (int k = 0; k < 16; k++) {
            float a[4], bb[4];
            #pragma unroll
            for (int i = 0; i < 4; i++) a[i]  = As[k][ty * 4 + i];
            #pragma unroll
            for (int j = 0; j < 4; j++) bb[j] = Bs[k][tx * 4 + j];
            #pragma unroll
            for (int i = 0; i < 4; i++)
                #pragma unroll
                for (int j = 0; j < 4; j++)
                    acc[i][j] = fmaf(a[i], bb[j], acc[i][j]);
        }
        __syncthreads();
    }

    #pragma unroll
    for (int i = 0; i < 4; i++) {
        int r = row0 + ty * 4 + i;
        #pragma unroll
        for (int j = 0; j < 4; j++) {
            int c = col0 + tx * 4 + j;
            O[r * HD + c] = acc[i][j] + b[c];
        }
    }
}

// ---------------------------------------------------------------------------
// Kernel 2: per-head scores.  S[h][n][m] = (Q[n,h,:]·K[m,h,:]) * 0.25
// NT GEMM, 64x64 tile, K-dim = D = 64 fully resident in smem.
// Smem stored d-major so inner loop uses conflict-free LDS.128.
// ---------------------------------------------------------------------------
__global__ void scores_kernel()
{
    const int h  = blockIdx.z;
    const int m0 = blockIdx.x * 64;   // key columns
    const int n0 = blockIdx.y * 64;   // query rows

    __shared__ __align__(16) float Qs[64][68];  // Qs[d][i]
    __shared__ __align__(16) float Ks[64][68];  // Ks[d][j]

    const int tid = threadIdx.x;      // 0..255

    #pragma unroll
    for (int l = 0; l < 16; l++) {
        int e = tid + l * 256;        // 0..4095
        int d = e & 63, i = e >> 6;   // global reads coalesced over d
        Qs[d][i] = g_Q[(size_t)(n0 + i) * HD + h * D + d];
        Ks[d][i] = g_K[(size_t)(m0 + i) * HD + h * D + d];
    }
    __syncthreads();

    const int tx = tid & 15;          // 0..15 -> 4 cols each
    const int ty = tid >> 4;          // 0..15 -> 4 rows each

    float acc[4][4] = {};
    #pragma unroll
    for (int d = 0; d < 64; d++) {
        float4 a4 = *reinterpret_cast<const float4*>(&Qs[d][ty * 4]);
        float4 b4 = *reinterpret_cast<const float4*>(&Ks[d][tx * 4]);
        float a[4] = {a4.x, a4.y, a4.z, a4.w};
        float bb[4] = {b4.x, b4.y, b4.z, b4.w};
        #pragma unroll
        for (int i = 0; i < 4; i++)
            #pragma unroll
            for (int j = 0; j < 4; j++)
                acc[i][j] = fmaf(a[i], bb[j], acc[i][j]);
    }

    #pragma unroll
    for (int i = 0; i < 4; i++) {
        size_t row = (size_t)h * NN + (n0 + ty * 4 + i);
        float4 v = make_float4(acc[i][0] * INV_SCALE, acc[i][1] * INV_SCALE,
                               acc[i][2] * INV_SCALE, acc[i][3] * INV_SCALE);
        *reinterpret_cast<float4*>(&g_S[row * NN + m0 + tx * 4]) = v;
    }
}

// ---------------------------------------------------------------------------
// Kernel 3: per-row softmax over each head + mean over heads.
// One block (256 threads) per query row n; each thread owns 16 columns.
// ---------------------------------------------------------------------------
__global__ void reduce_kernel(float* __restrict__ out)
{
    const int n   = blockIdx.x;
    const int tid = threadIdx.x;
    const int lane = tid & 31;
    const int warp = tid >> 5;

    __shared__ float red[64];

    float acc[16];
    #pragma unroll
    for (int j = 0; j < 16; j++) acc[j] = 0.0f;

    for (int h = 0; h < H; h++) {
        const float* __restrict__ Srow = g_S + ((size_t)h * NN + n) * NN;
        float s[16];
        float mx = -1e30f;
        #pragma unroll
        for (int j = 0; j < 16; j++) {
            s[j] = Srow[tid + j * 256];
            mx = fmaxf(mx, s[j]);
        }
        // block max
        #pragma unroll
        for (int o = 16; o; o >>= 1) mx = fmaxf(mx, __shfl_xor_sync(0xffffffffu, mx, o));
        if (lane == 0) red[warp] = mx;
        __syncthreads();
        if (tid == 0) {
            float v = red[0];
            #pragma unroll
            for (int w = 1; w < 8; w++) v = fmaxf(v, red[w]);
            red[32] = v;
        }
        __syncthreads();
        const float bm = red[32];

        float lsum = 0.0f;
        #pragma unroll
        for (int j = 0; j < 16; j++) {
            s[j] = __expf(s[j] - bm);
            lsum += s[j];
        }
        // block sum
        #pragma unroll
        for (int o = 16; o; o >>= 1) lsum += __shfl_xor_sync(0xffffffffu, lsum, o);
        if (lane == 0) red[warp] = lsum;
        __syncthreads();
        if (tid == 0) {
            float v = red[0];
            #pragma unroll
            for (int w = 1; w < 8; w++) v += red[w];
            red[33] = v;
        }
        __syncthreads();
        const float inv = 1.0f / red[33];
        #pragma unroll
        for (int j = 0; j < 16; j++) acc[j] += s[j] * inv;
        __syncthreads();   // red reused next head
    }

    float* __restrict__ orow = out + (size_t)n * NN;
    const float invH = 1.0f / (float)H;
    #pragma unroll
    for (int j = 0; j < 16; j++) orow[tid + j * 256] = acc[j] * invH;
}

// ---------------------------------------------------------------------------
extern "C" void kernel_launch(void* const* d_in, const int* in_sizes, int n_in,
                              void* d_out, int out_size)
{
    const float* X  = (const float*)d_in[0];   // node_features [4096, 256]
    const float* Wq = (const float*)d_in[1];   // [256, 512]
    const float* bq = (const float*)d_in[2];   // [512]
    const float* Wk = (const float*)d_in[3];   // [256, 512]
    const float* bk = (const float*)d_in[4];   // [512]
    float* out = (float*)d_out;                // [4096, 4096]

    (void)in_sizes; (void)n_in; (void)out_size;

    {
        dim3 grid(HD / 64, NN / 64, 2);
        proj_kernel<<<grid, 256>>>(X, Wq, bq, Wk, bk);
    }
    {
        dim3 grid(NN / 64, NN / 64, H);
        scores_kernel<<<grid, 256>>>();
    }
    {
        reduce_kernel<<<NN, 256>>>(out);
    }
}

// round 3
// speedup vs baseline: 1.9512x; 1.9512x over previous
#include <cuda_runtime.h>
#include <cuda_bf16.h>
#include <cstdint>
#include <math.h>

#define NN    4096
#define IN_F  256
#define H     8
#define D     64
#define HD    (H * D)          // 512
#define INV_SCALE 0.25f        // 1 / (8.0 * 0.5)

// ---------------------------------------------------------------------------
// Scratch (__device__ globals: allocation-free rule)
// ---------------------------------------------------------------------------
__device__ float g_S[(size_t)H * NN * NN];                 // 512 MB scores
__device__ __nv_bfloat16 g_Qhi[NN * HD];
__device__ __nv_bfloat16 g_Qlo[NN * HD];
__device__ __nv_bfloat16 g_Khi[NN * HD];
__device__ __nv_bfloat16 g_Klo[NN * HD];

// ---------------------------------------------------------------------------
// Warp MMA helpers (sm_80+ path — tcgen05 unavailable on compute_100 target)
// ---------------------------------------------------------------------------
__device__ __forceinline__ uint32_t smem_u32(const void* p) {
    uint32_t a;
    asm("{ .reg .u64 t; cvta.to.shared.u64 t, %1; cvt.u32.u64 %0, t; }"
        : "=r"(a) : "l"(p));
    return a;
}

__device__ __forceinline__ void ldsm_x4(uint32_t (&r)[4], uint32_t addr) {
    asm volatile("ldmatrix.sync.aligned.m8n8.x4.shared.b16 {%0,%1,%2,%3}, [%4];"
                 : "=r"(r[0]), "=r"(r[1]), "=r"(r[2]), "=r"(r[3]) : "r"(addr));
}

__device__ __forceinline__ void mma16816(float (&d)[4], const uint32_t (&a)[4],
                                         uint32_t b0, uint32_t b1) {
    asm volatile(
        "mma.sync.aligned.m16n8k16.row.col.f32.bf16.bf16.f32 "
        "{%0,%1,%2,%3}, {%4,%5,%6,%7}, {%8,%9}, {%0,%1,%2,%3};"
        : "+f"(d[0]), "+f"(d[1]), "+f"(d[2]), "+f"(d[3])
        : "r"(a[0]), "r"(a[1]), "r"(a[2]), "r"(a[3]), "r"(b0), "r"(b1));
}

// ---------------------------------------------------------------------------
// Kernel 1: Q/K projection (fp32 CUDA cores), epilogue splits to bf16 hi/lo.
// ---------------------------------------------------------------------------
__global__ void proj_kernel(const float* __restrict__ X,
                            const float* __restrict__ Wq, const float* __restrict__ bq,
                            const float* __restrict__ Wk, const float* __restrict__ bk)
{
    const float* W = (blockIdx.z == 0) ? Wq : Wk;
    const float* b = (blockIdx.z == 0) ? bq : bk;
    __nv_bfloat16* Ohi = (blockIdx.z == 0) ? g_Qhi : g_Khi;
    __nv_bfloat16* Olo = (blockIdx.z == 0) ? g_Qlo : g_Klo;

    __shared__ float As[16][68];
    __shared__ float Bs[16][68];

    const int tid  = threadIdx.x;
    const int row0 = blockIdx.y * 64;
    const int col0 = blockIdx.x * 64;
    const int tx   = tid & 15;
    const int ty   = tid >> 4;

    float acc[4][4] = {};

    for (int k0 = 0; k0 < IN_F; k0 += 16) {
        #pragma unroll
        for (int l = 0; l < 4; l++) {
            int e = tid + l * 256;
            int k = e & 15, i = e >> 4;
            As[k][i] = X[(row0 + i) * IN_F + k0 + k];
        }
        #pragma unroll
        for (int l = 0; l < 4; l++) {
            int e = tid + l * 256;
            int j = e & 63, k = e >> 6;
            Bs[k][j] = W[(k0 + k) * HD + col0 + j];
        }
        __syncthreads();
        #pragma unroll
        for (int k = 0; k < 16; k++) {
            float a[4], bb[4];
            #pragma unroll
            for (int i = 0; i < 4; i++) a[i]  = As[k][ty * 4 + i];
            #pragma unroll
            for (int j = 0; j < 4; j++) bb[j] = Bs[k][tx * 4 + j];
            #pragma unroll
            for (int i = 0; i < 4; i++)
                #pragma unroll
                for (int j = 0; j < 4; j++)
                    acc[i][j] = fmaf(a[i], bb[j], acc[i][j]);
        }
        __syncthreads();
    }

    #pragma unroll
    for (int i = 0; i < 4; i++) {
        int r = row0 + ty * 4 + i;
        #pragma unroll
        for (int j = 0; j < 4; j++) {
            int c = col0 + tx * 4 + j;
            float v = acc[i][j] + b[c];
            __nv_bfloat16 hi = __float2bfloat16(v);
            __nv_bfloat16 lo = __float2bfloat16(v - __bfloat162float(hi));
            Ohi[r * HD + c] = hi;
            Olo[r * HD + c] = lo;
        }
    }
}

// ---------------------------------------------------------------------------
// Kernel 2: scores via warp-level HMMA (mma.sync.m16n8k16.bf16, 3-term split).
// CTA: 128x128 output tile, 256 threads (8 warps, each 64x32).
// K=64 resident in smem (hi+lo for both operands), XOR-swizzled 16B chunks.
// ---------------------------------------------------------------------------
#define A_HI 0
#define A_LO 16384
#define B_HI 32768
#define B_LO 49152
#define SCORES_SMEM 65536

__global__ void __launch_bounds__(256)
scores_kernel()
{
    extern __shared__ char sm[];
    const uint32_t smb = smem_u32(sm);

    const int tid  = threadIdx.x;
    const int wid  = tid >> 5;
    const int lane = tid & 31;

    const int h  = blockIdx.z;
    const int m0 = blockIdx.x * 128;   // key rows   (gemm N)
    const int n0 = blockIdx.y * 128;   // query rows (gemm M)

    // ---- load 4 tiles (128 rows x 64 bf16 = 16 KB each), swizzled 16B chunks
    #pragma unroll
    for (int it = 0; it < 4; it++) {
        int e   = tid + it * 256;        // 0..1023
        int row = e >> 3;
        int c   = e & 7;
        uint32_t dstoff = (uint32_t)(row * 128 + ((c ^ (row & 7)) * 16));
        size_t gq = (size_t)(n0 + row) * HD + h * D + c * 8;
        size_t gk = (size_t)(m0 + row) * HD + h * D + c * 8;
        *reinterpret_cast<uint4*>(sm + A_HI + dstoff) =
            *reinterpret_cast<const uint4*>(g_Qhi + gq);
        *reinterpret_cast<uint4*>(sm + A_LO + dstoff) =
            *reinterpret_cast<const uint4*>(g_Qlo + gq);
        *reinterpret_cast<uint4*>(sm + B_HI + dstoff) =
            *reinterpret_cast<const uint4*>(g_Khi + gk);
        *reinterpret_cast<uint4*>(sm + B_LO + dstoff) =
            *reinterpret_cast<const uint4*>(g_Klo + gk);
    }
    __syncthreads();

    // warp tile: 64 (M) x 32 (N)
    const int m_base = (wid & 1) * 64;
    const int n_base = (wid >> 1) * 32;

    // per-lane ldmatrix row/chunk selectors
    const int xr      = lane & 7;
    const int a_row   = (lane & 7) + ((lane >> 3) & 1) * 8;   // within 16-row subtile
    const int a_half  = lane >> 4;                            // 0/1 -> lo/hi 16B of k-step
    const int b_row   = (lane & 7) + ((lane >> 4) ? 8 : 0);
    const int b_half  = (lane >> 3) & 1;

    float acc[4][4][4];   // [mi][nj][frag]
    #pragma unroll
    for (int mi = 0; mi < 4; mi++)
        #pragma unroll
        for (int nj = 0; nj < 4; nj++)
            #pragma unroll
            for (int f = 0; f < 4; f++) acc[mi][nj][f] = 0.0f;

    // 3 terms: (Ahi,Bhi), (Ahi,Blo), (Alo,Bhi)
    const uint32_t a_off[3] = {A_HI, A_HI, A_LO};
    const uint32_t b_off[3] = {B_HI, B_LO, B_HI};

    #pragma unroll
    for (int t = 0; t < 3; t++) {
        const uint32_t Ab = smb + a_off[t];
        const uint32_t Bb = smb + b_off[t];
        #pragma unroll
        for (int k = 0; k < 4; k++) {
            uint32_t af[4][4];
            #pragma unroll
            for (int mi = 0; mi < 4; mi++) {
                int row = m_base + mi * 16 + a_row;
                uint32_t addr = Ab + row * 128 + (((2 * k + a_half) ^ xr) * 16);
                ldsm_x4(af[mi], addr);
            }
            uint32_t bf[2][4];
            #pragma unroll
            for (int nb = 0; nb < 2; nb++) {
                int row = n_base + nb * 16 + b_row;
                uint32_t addr = Bb + row * 128 + (((2 * k + b_half) ^ xr) * 16);
                ldsm_x4(bf[nb], addr);
            }
            #pragma unroll
            for (int mi = 0; mi < 4; mi++) {
                mma16816(acc[mi][0], af[mi], bf[0][0], bf[0][1]);
                mma16816(acc[mi][1], af[mi], bf[0][2], bf[0][3]);
                mma16816(acc[mi][2], af[mi], bf[1][0], bf[1][1]);
                mma16816(acc[mi][3], af[mi], bf[1][2], bf[1][3]);
            }
        }
    }

    // ---- epilogue: scale + store.  d-frag: lane g=l>>2, t=l&3:
    //   d0,d1 -> (row m+g,   col n + 2t, 2t+1)
    //   d2,d3 -> (row m+g+8, same cols)
    const int g = lane >> 2;
    const int q = lane & 3;
    #pragma unroll
    for (int mi = 0; mi < 4; mi++) {
        int r0 = n0 + m_base + mi * 16 + g;
        float* __restrict__ p0 = g_S + ((size_t)h * NN + r0) * NN;
        float* __restrict__ p1 = g_S + ((size_t)h * NN + r0 + 8) * NN;
        #pragma unroll
        for (int nj = 0; nj < 4; nj++) {
            int c = m0 + n_base + nj * 8 + 2 * q;
            float2 v0 = make_float2(acc[mi][nj][0] * INV_SCALE,
                                    acc[mi][nj][1] * INV_SCALE);
            float2 v1 = make_float2(acc[mi][nj][2] * INV_SCALE,
                                    acc[mi][nj][3] * INV_SCALE);
            *reinterpret_cast<float2*>(p0 + c) = v0;
            *reinterpret_cast<float2*>(p1 + c) = v1;
        }
    }
}

// ---------------------------------------------------------------------------
// Kernel 3: per-row softmax over each head + mean over heads.
// ---------------------------------------------------------------------------
__global__ void reduce_kernel(float* __restrict__ out)
{
    const int n    = blockIdx.x;
    const int tid  = threadIdx.x;
    const int lane = tid & 31;
    const int warp = tid >> 5;

    __shared__ float red[64];

    float acc[16];
    #pragma unroll
    for (int j = 0; j < 16; j++) acc[j] = 0.0f;

    for (int h = 0; h < H; h++) {
        const float* __restrict__ Srow = g_S + ((size_t)h * NN + n) * NN;
        float s[16];
        float mx = -1e30f;
        #pragma unroll
        for (int j = 0; j < 16; j++) {
            s[j] = Srow[tid + j * 256];
            mx = fmaxf(mx, s[j]);
        }
        #pragma unroll
        for (int o = 16; o; o >>= 1) mx = fmaxf(mx, __shfl_xor_sync(0xffffffffu, mx, o));
        if (lane == 0) red[warp] = mx;
        __syncthreads();
        if (tid == 0) {
            float v = red[0];
            #pragma unroll
            for (int w = 1; w < 8; w++) v = fmaxf(v, red[w]);
            red[32] = v;
        }
        __syncthreads();
        const float bm = red[32];

        float lsum = 0.0f;
        #pragma unroll
        for (int j = 0; j < 16; j++) {
            s[j] = __expf(s[j] - bm);
            lsum += s[j];
        }
        #pragma unroll
        for (int o = 16; o; o >>= 1) lsum += __shfl_xor_sync(0xffffffffu, lsum, o);
        if (lane == 0) red[warp] = lsum;
        __syncthreads();
        if (tid == 0) {
            float v = red[0];
            #pragma unroll
            for (int w = 1; w < 8; w++) v += red[w];
            red[33] = v;
        }
        __syncthreads();
        const float inv = 1.0f / red[33];
        #pragma unroll
        for (int j = 0; j < 16; j++) acc[j] += s[j] * inv;
        __syncthreads();
    }

    float* __restrict__ orow = out + (size_t)n * NN;
    const float invH = 1.0f / (float)H;
    #pragma unroll
    for (int j = 0; j < 16; j++) orow[tid + j * 256] = acc[j] * invH;
}

// ---------------------------------------------------------------------------
extern "C" void kernel_launch(void* const* d_in, const int* in_sizes, int n_in,
                              void* d_out, int out_size)
{
    const float* X  = (const float*)d_in[0];
    const float* Wq = (const float*)d_in[1];
    const float* bq = (const float*)d_in[2];
    const float* Wk = (const float*)d_in[3];
    const float* bk = (const float*)d_in[4];
    float* out = (float*)d_out;

    (void)in_sizes; (void)n_in; (void)out_size;

    // idempotent, host-side, not stream work; called every time (no static guard)
    cudaFuncSetAttribute(scores_kernel,
                         cudaFuncAttributeMaxDynamicSharedMemorySize, SCORES_SMEM);

    {
        dim3 grid(HD / 64, NN / 64, 2);
        proj_kernel<<<grid, 256>>>(X, Wq, bq, Wk, bk);
    }
    {
        dim3 grid(NN / 128, NN / 128, H);
        scores_kernel<<<grid, 256, SCORES_SMEM>>>();
    }
    reduce_kernel<<<NN, 256>>>(out);
}